// round 11
// baseline (speedup 1.0000x reference)
#include <cuda_runtime.h>

// Problem constants
#define TT   16
#define BB   512
#define NIN  3072
#define SS1  256
#define SS2  256
#define SS3  128
#define EE   8
#define DECAYF 0.95f
#define KCHUNK 512   // confirmed reference k-partition: 512-chunks, serial fold

typedef unsigned long long ull;

// Persistent scratch (allocation-free: __device__ globals)
__device__ float g_H1[(size_t)EE * TT * BB * SS1]; // 67 MB
__device__ float g_H2[(size_t)EE * TT * BB * SS2]; // 67 MB
__device__ float g_H3[(size_t)EE * TT * BB * SS3]; // 33 MB
__device__ float g_C1[(size_t)TT * BB * SS1];      // 8.4 MB
__device__ float g_C2[(size_t)TT * BB * SS2];      // 8.4 MB

// ---- packed f32x2 helpers (each half is an independent rn op: bit-exact
//      with the scalar serial chain) ------------------------------------
__device__ __forceinline__ ull fma2(ull a, ull b, ull c) {
    asm("fma.rn.f32x2 %0, %1, %2, %0;" : "+l"(c) : "l"(a), "l"(b));
    return c;
}
__device__ __forceinline__ ull add2(ull a, ull b) {
    ull r; asm("add.rn.f32x2 %0, %1, %2;" : "=l"(r) : "l"(a), "l"(b));
    return r;
}
__device__ __forceinline__ ull dup2(float x) {
    ull r; asm("mov.b64 %0, {%1, %1};" : "=l"(r) : "f"(x));
    return r;
}
__device__ __forceinline__ float2 unpk(ull a) {
    float2 r; asm("mov.b64 {%0, %1}, %2;" : "=f"(r.x), "=f"(r.y) : "l"(a));
    return r;
}

// ---------------------------------------------------------------------------
// Batched NT SGEMM, k-chunked (PC) fp32 accumulation, packed f32x2 math:
//   per chunk: fresh accumulator, strictly ascending rn-FMA chain;
//   chunks folded serially ascending with one rn-add each (accC starts 0).
// Each f32x2 half reproduces the scalar chain bit-for-bit.
// BM=128, BN=64, BK=32, 256 threads, 8x4 microtile packed as 4 (row-pair) x 4.
// M % 128 == 0, N % 64 == 0, K % 32 == 0, PC % 32 == 0.
// ---------------------------------------------------------------------------
__global__ void __launch_bounds__(256) gemm_f32x2(
    const float* __restrict__ X,   // [M][K]
    const float* __restrict__ W,   // [E][N][K]
    float* __restrict__ H,         // [E][M][N]
    int M, int N, int K, int PC)
{
    const int BM = 128, BN = 64, BK = 32;
    __shared__ float Xs[BK][BM];   // 16 KB, k-major
    __shared__ ull   Wd[BK][BN];   // 16 KB, duplicated (w,w) pairs

    const int e  = blockIdx.z;
    const int m0 = blockIdx.x * BM;
    const int n0 = blockIdx.y * BN;
    const float* Xp = X + (size_t)m0 * K;
    const float* Wp = W + (size_t)e * N * K + (size_t)n0 * K;
    float*       Hp = H + (size_t)e * M * N;

    const int tid = threadIdx.x;
    const int xr_ = tid >> 1, xc_ = (tid & 1) * 16;  // X loader: 4 float4
    const int wr_ = tid >> 2, wc_ = (tid & 3) * 8;   // W loader: 2 float4
    const int ty  = tid >> 4, tx = tid & 15;         // 8-row x 4-col microtile

    ull accC[4][4], accP[4][4];
    #pragma unroll
    for (int p = 0; p < 4; p++)
        #pragma unroll
        for (int j = 0; j < 4; j++) { accC[p][j] = 0ULL; accP[p][j] = 0ULL; }

    for (int k0 = 0; k0 < K; k0 += BK) {
        #pragma unroll
        for (int q = 0; q < 4; q++) {
            float4 v = *reinterpret_cast<const float4*>(
                &Xp[(size_t)xr_ * K + k0 + xc_ + q * 4]);
            Xs[xc_ + q*4 + 0][xr_] = v.x; Xs[xc_ + q*4 + 1][xr_] = v.y;
            Xs[xc_ + q*4 + 2][xr_] = v.z; Xs[xc_ + q*4 + 3][xr_] = v.w;
        }
        #pragma unroll
        for (int q = 0; q < 2; q++) {
            float4 v = *reinterpret_cast<const float4*>(
                &Wp[(size_t)wr_ * K + k0 + wc_ + q * 4]);
            Wd[wc_ + q*4 + 0][wr_] = dup2(v.x); Wd[wc_ + q*4 + 1][wr_] = dup2(v.y);
            Wd[wc_ + q*4 + 2][wr_] = dup2(v.z); Wd[wc_ + q*4 + 3][wr_] = dup2(v.w);
        }
        __syncthreads();

        #pragma unroll
        for (int kk = 0; kk < BK; kk++) {   // strictly ascending k
            ull xp[4], wp[4];
            #pragma unroll
            for (int p = 0; p < 4; p++)     // (row 2p, row 2p+1) pair, LDS.64
                xp[p] = *reinterpret_cast<const ull*>(&Xs[kk][ty * 8 + p * 2]);
            #pragma unroll
            for (int j = 0; j < 4; j++)     // (w,w) broadcast pair, LDS.64
                wp[j] = Wd[kk][tx * 4 + j];
            #pragma unroll
            for (int p = 0; p < 4; p++)
                #pragma unroll
                for (int j = 0; j < 4; j++)
                    accP[p][j] = fma2(xp[p], wp[j], accP[p][j]);
        }

        // Chunk boundary (PC % BK == 0): fold with one rn-add, reset.
        if (((k0 + BK) % PC) == 0) {
            #pragma unroll
            for (int p = 0; p < 4; p++)
                #pragma unroll
                for (int j = 0; j < 4; j++) {
                    accC[p][j] = add2(accC[p][j], accP[p][j]);
                    accP[p][j] = 0ULL;
                }
        }
        __syncthreads();
    }

    // Tail fold (K < PC or K % PC != 0); x + 0.0f is bitwise a no-op when
    // the last fold already landed exactly at K.
    #pragma unroll
    for (int p = 0; p < 4; p++) {
        float lo[4], hi[4];
        #pragma unroll
        for (int j = 0; j < 4; j++) {
            float2 r = unpk(add2(accC[p][j], accP[p][j]));
            lo[j] = r.x; hi[j] = r.y;
        }
        *reinterpret_cast<float4*>(
            &Hp[(size_t)(m0 + ty*8 + 2*p    ) * N + n0 + tx*4]) =
            make_float4(lo[0], lo[1], lo[2], lo[3]);
        *reinterpret_cast<float4*>(
            &Hp[(size_t)(m0 + ty*8 + 2*p + 1) * N + n0 + tx*4]) =
            make_float4(hi[0], hi[1], hi[2], hi[3]);
    }
}

// ---------------------------------------------------------------------------
// LIF scan over ALL timesteps for one stage. One thread per (b,o) element;
// membrane state for the 8 experts lives in registers; t-loop inside.
// Per-element arithmetic identical to the per-t kernel (separate-rounding):
//   v = rn(rn(v*0.95) + h) ; spk = (v>=1) ; v = rn(v - spk)
//   c = sum_e g[e]*spk (exact 1/64 multiples);  mean = (sum_t c) * 1/16
//   (sum_t c is exact: multiples of 1/8 bounded by 16; *1/16 exact.)
// ---------------------------------------------------------------------------
__global__ void lif_scan(
    const float* __restrict__ H,    // [E][T][n] pre-activations
    const float* __restrict__ g,
    float* __restrict__ Cout,       // [T][n] combined outputs (null: skip)
    float* __restrict__ Omean,      // [n] time-averaged output
    int n, size_t estride)          // estride = T*n
{
    int idx = blockIdx.x * blockDim.x + threadIdx.x;
    if (idx >= n) return;
    float gv[EE], v[EE];
    #pragma unroll
    for (int e = 0; e < EE; e++) { gv[e] = __ldg(&g[e]); v[e] = 0.f; }
    float osum = 0.f;
    for (int t = 0; t < TT; t++) {
        float c = 0.f;
        #pragma unroll
        for (int e = 0; e < EE; e++) {
            float h  = H[(size_t)e * estride + (size_t)t * n + idx];
            float vv = __fadd_rn(__fmul_rn(v[e], DECAYF), h);
            float spk = (vv >= 1.0f) ? 1.0f : 0.0f;
            v[e] = __fsub_rn(vv, spk);
            c = __fadd_rn(c, __fmul_rn(gv[e], spk));
        }
        if (Cout) Cout[(size_t)t * n + idx] = c;
        osum = __fadd_rn(osum, c);
    }
    Omean[idx] = __fmul_rn(osum, 1.0f / (float)TT);
}

// ---------------------------------------------------------------------------
extern "C" void kernel_launch(void* const* d_in, const int* in_sizes, int n_in,
                              void* d_out, int out_size) {
    const float* X  = (const float*)d_in[0];  // [16][512][3072]
    const float* W1 = (const float*)d_in[1];  // [8][256][3072]
    const float* W2 = (const float*)d_in[2];  // [8][256][256]
    const float* W3 = (const float*)d_in[3];  // [8][128][256]
    const float* g1 = (const float*)d_in[4];
    const float* g2 = (const float*)d_in[5];
    const float* g3 = (const float*)d_in[6];
    float* out = (float*)d_out;

    float *H1, *H2, *H3, *C1, *C2;
    cudaGetSymbolAddress((void**)&H1, g_H1);
    cudaGetSymbolAddress((void**)&H2, g_H2);
    cudaGetSymbolAddress((void**)&H3, g_H3);
    cudaGetSymbolAddress((void**)&C1, g_C1);
    cudaGetSymbolAddress((void**)&C2, g_C2);

    const int M  = TT * BB;              // 8192 rows = (t,b)
    const int n1 = BB * SS1, n2 = BB * SS2, n3 = BB * SS3;

    // Stage 1: one batched GEMM for all t (time-independent), 512-chunk fold.
    gemm_f32x2<<<dim3(M/128, SS1/64, EE), 256>>>(X,  W1, H1, M, SS1, NIN, KCHUNK);
    // Stage-1 LIF scan: all 16 timesteps, state in registers.
    lif_scan<<<(n1 + 255)/256, 256>>>(H1, g1, C1, out,            n1, (size_t)TT * n1);
    // Stage 2: batched over all t (K=256 < 512 -> single serial chain).
    gemm_f32x2<<<dim3(M/128, SS2/64, EE), 256>>>(C1, W2, H2, M, SS2, SS1, KCHUNK);
    lif_scan<<<(n2 + 255)/256, 256>>>(H2, g2, C2, out + n1,       n2, (size_t)TT * n2);
    // Stage 3: batched over all t.
    gemm_f32x2<<<dim3(M/128, SS3/64, EE), 256>>>(C2, W3, H3, M, SS3, SS2, KCHUNK);
    lif_scan<<<(n3 + 255)/256, 256>>>(H3, g3, nullptr, out + n1 + n2, n3, (size_t)TT * n3);
}

// round 12
// speedup vs baseline: 1.6045x; 1.6045x over previous
#include <cuda_runtime.h>

// Problem constants
#define TT   16
#define BB   512
#define NIN  3072
#define SS1  256
#define SS2  256
#define SS3  128
#define EE   8
#define DECAYF 0.95f
#define KCHUNK 512   // confirmed reference k-partition: 512-chunks, serial ascending fold

typedef unsigned long long ull;

// Persistent scratch (allocation-free: __device__ globals)
__device__ float g_H1[(size_t)EE * TT * BB * SS1]; // 67 MB
__device__ float g_H2[(size_t)EE * TT * BB * SS2]; // 67 MB
__device__ float g_H3[(size_t)EE * TT * BB * SS3]; // 33 MB
__device__ float g_C1[(size_t)TT * BB * SS1];      // 8.4 MB
__device__ float g_C2[(size_t)TT * BB * SS2];      // 8.4 MB

// ---- packed f32x2 helpers: each half is an independent rn op, bit-exact
//      vs the scalar serial chain (verified rel_err==0.0 in R11) ----------
__device__ __forceinline__ ull fma2(ull a, ull b, ull c) {
    asm("fma.rn.f32x2 %0, %1, %2, %0;" : "+l"(c) : "l"(a), "l"(b));
    return c;
}
__device__ __forceinline__ ull dup2(float x) {
    ull r; asm("mov.b64 %0, {%1, %1};" : "=l"(r) : "f"(x));
    return r;
}
__device__ __forceinline__ float2 unpk(ull a) {
    float2 r; asm("mov.b64 {%0, %1}, %2;" : "=f"(r.x), "=f"(r.y) : "l"(a));
    return r;
}

// ---------------------------------------------------------------------------
// Batched NT SGEMM, k-chunked (PC=512) fp32 accumulation, packed f32x2 math.
//   per chunk: fresh accumulator, strictly ascending rn-FMA chain;
//   chunks folded serially ascending via gmem RMW: H = rn(H + P_c)
//   (same CTA owns its tile across all chunks -> no race; bit-identical
//   to the register fold). Stages 2/3 (K < PC) degrade to one plain store.
// BM=128, BN=128, BK=32, 256 threads; microtile 8 rows (4 f32x2 row-pairs)
// x 8 cols; thread tx owns columns {j*16+tx} so W smem reads are
// conflict-free (16 consecutive ull per LDS.64). X reads are ty-broadcast.
// M%128==0, N%128==0, K%32==0, PC%32==0.
// ---------------------------------------------------------------------------
__global__ void __launch_bounds__(256, 2) gemm_f32x2(
    const float* __restrict__ X,   // [M][K]
    const float* __restrict__ W,   // [E][N][K]
    float* __restrict__ H,         // [E][M][N]
    int M, int N, int K, int PC)
{
    const int BK = 32, BM = 128, BN = 128;
    __shared__ float Xs[BK * BM];  // 16 KB, k-major: Xs[k*BM + m]
    __shared__ ull   Wd[BK * BN];  // 32 KB, k-major duplicated: Wd[k*BN + n]

    const int e  = blockIdx.z;
    const int m0 = blockIdx.x * BM;
    const int n0 = blockIdx.y * BN;
    const float* Xp = X + (size_t)m0 * K;
    const float* Wp = W + (size_t)e * N * K + (size_t)n0 * K;
    float*       Hp = H + (size_t)e * M * N;

    const int tid = threadIdx.x;
    const int lr  = tid >> 1;            // loader row 0..127
    const int lc  = (tid & 1) * 16;      // loader k-offset 0 / 16
    const int ty  = tid >> 4;            // 0..15: rows ty*8 .. ty*8+7
    const int tx  = tid & 15;            // 0..15: cols {j*16+tx}

    ull accP[4][8];
    #pragma unroll
    for (int p = 0; p < 4; p++)
        #pragma unroll
        for (int j = 0; j < 8; j++) accP[p][j] = 0ULL;

    bool first = true;

    auto fold = [&]() {   // serial ascending chunk fold into gmem (rn adds)
        #pragma unroll
        for (int p = 0; p < 4; p++) {
            size_t i0 = (size_t)(m0 + ty * 8 + 2 * p) * N + n0 + tx;
            #pragma unroll
            for (int j = 0; j < 8; j++) {
                float2 r = unpk(accP[p][j]);
                size_t a0 = i0 + j * 16, a1 = a0 + N;
                if (first) { Hp[a0] = r.x; Hp[a1] = r.y; }
                else {
                    Hp[a0] = __fadd_rn(Hp[a0], r.x);
                    Hp[a1] = __fadd_rn(Hp[a1], r.y);
                }
                accP[p][j] = 0ULL;
            }
        }
    };

    for (int k0 = 0; k0 < K; k0 += BK) {
        float4 xv[4], wv[4];
        #pragma unroll
        for (int q = 0; q < 4; q++)
            xv[q] = *reinterpret_cast<const float4*>(
                &Xp[(size_t)lr * K + k0 + lc + q * 4]);
        #pragma unroll
        for (int q = 0; q < 4; q++)
            wv[q] = *reinterpret_cast<const float4*>(
                &Wp[(size_t)lr * K + k0 + lc + q * 4]);

        __syncthreads();   // previous compute done before smem overwrite
        #pragma unroll
        for (int q = 0; q < 4; q++) {
            int kq = lc + q * 4;
            Xs[(kq + 0) * BM + lr] = xv[q].x;
            Xs[(kq + 1) * BM + lr] = xv[q].y;
            Xs[(kq + 2) * BM + lr] = xv[q].z;
            Xs[(kq + 3) * BM + lr] = xv[q].w;
            Wd[(kq + 0) * BN + lr] = dup2(wv[q].x);
            Wd[(kq + 1) * BN + lr] = dup2(wv[q].y);
            Wd[(kq + 2) * BN + lr] = dup2(wv[q].z);
            Wd[(kq + 3) * BN + lr] = dup2(wv[q].w);
        }
        __syncthreads();

        #pragma unroll
        for (int kk = 0; kk < BK; kk++) {   // strictly ascending k
            ull xp[4], wp[8];
            const ull* xrow = reinterpret_cast<const ull*>(Xs + kk * BM) + ty * 4;
            #pragma unroll
            for (int p = 0; p < 4; p++) xp[p] = xrow[p];       // row pair, broadcast
            #pragma unroll
            for (int j = 0; j < 8; j++) wp[j] = Wd[kk * BN + j * 16 + tx]; // conflict-free
            #pragma unroll
            for (int p = 0; p < 4; p++)
                #pragma unroll
                for (int j = 0; j < 8; j++)
                    accP[p][j] = fma2(xp[p], wp[j], accP[p][j]);
        }

        // 512-chunk boundary: fold into H (ascending), reset accumulator.
        if (((k0 + BK) % PC) == 0) { fold(); first = false; }
    }
    // Tail chunk (K < PC or K % PC != 0): stages 2/3 land here with
    // first==true -> plain store of the single serial chain.
    if ((K % PC) != 0) fold();
}

// ---------------------------------------------------------------------------
// LIF scan over ALL timesteps for one stage. One thread per (b,o) element;
// membrane state for the 8 experts in registers; t-loop inside.
//   v = rn(rn(v*0.95) + h) ; spk = (v>=1) ; v = rn(v - spk)
//   c = sum_e g[e]*spk (exact 1/64 multiples);  mean = (sum_t c) * 1/16
// ---------------------------------------------------------------------------
__global__ void lif_scan(
    const float* __restrict__ H,    // [E][T][n] pre-activations
    const float* __restrict__ g,
    float* __restrict__ Cout,       // [T][n] combined outputs (null: skip)
    float* __restrict__ Omean,      // [n] time-averaged output
    int n, size_t estride)          // estride = T*n
{
    int idx = blockIdx.x * blockDim.x + threadIdx.x;
    if (idx >= n) return;
    float gv[EE], v[EE];
    #pragma unroll
    for (int e = 0; e < EE; e++) { gv[e] = __ldg(&g[e]); v[e] = 0.f; }
    float osum = 0.f;
    for (int t = 0; t < TT; t++) {
        float c = 0.f;
        #pragma unroll
        for (int e = 0; e < EE; e++) {
            float h  = H[(size_t)e * estride + (size_t)t * n + idx];
            float vv = __fadd_rn(__fmul_rn(v[e], DECAYF), h);
            float spk = (vv >= 1.0f) ? 1.0f : 0.0f;
            v[e] = __fsub_rn(vv, spk);
            c = __fadd_rn(c, __fmul_rn(gv[e], spk));
        }
        if (Cout) Cout[(size_t)t * n + idx] = c;
        osum = __fadd_rn(osum, c);
    }
    Omean[idx] = __fmul_rn(osum, 1.0f / (float)TT);
}

// ---------------------------------------------------------------------------
extern "C" void kernel_launch(void* const* d_in, const int* in_sizes, int n_in,
                              void* d_out, int out_size) {
    const float* X  = (const float*)d_in[0];  // [16][512][3072]
    const float* W1 = (const float*)d_in[1];  // [8][256][3072]
    const float* W2 = (const float*)d_in[2];  // [8][256][256]
    const float* W3 = (const float*)d_in[3];  // [8][128][256]
    const float* g1 = (const float*)d_in[4];
    const float* g2 = (const float*)d_in[5];
    const float* g3 = (const float*)d_in[6];
    float* out = (float*)d_out;

    float *H1, *H2, *H3, *C1, *C2;
    cudaGetSymbolAddress((void**)&H1, g_H1);
    cudaGetSymbolAddress((void**)&H2, g_H2);
    cudaGetSymbolAddress((void**)&H3, g_H3);
    cudaGetSymbolAddress((void**)&C1, g_C1);
    cudaGetSymbolAddress((void**)&C2, g_C2);

    const int M  = TT * BB;              // 8192 rows = (t,b)
    const int n1 = BB * SS1, n2 = BB * SS2, n3 = BB * SS3;

    // Stage 1: one batched GEMM for all t, 512-chunk serial fold.
    gemm_f32x2<<<dim3(M/128, SS1/128, EE), 256>>>(X,  W1, H1, M, SS1, NIN, KCHUNK);
    lif_scan<<<(n1 + 255)/256, 256>>>(H1, g1, C1, out,            n1, (size_t)TT * n1);
    // Stage 2: batched over all t (K=256 < 512 -> single serial chain).
    gemm_f32x2<<<dim3(M/128, SS2/128, EE), 256>>>(C1, W2, H2, M, SS2, SS1, KCHUNK);
    lif_scan<<<(n2 + 255)/256, 256>>>(H2, g2, C2, out + n1,       n2, (size_t)TT * n2);
    // Stage 3: batched over all t.
    gemm_f32x2<<<dim3(M/128, SS3/128, EE), 256>>>(C2, W3, H3, M, SS3, SS2, KCHUNK);
    lif_scan<<<(n3 + 255)/256, 256>>>(H3, g3, nullptr, out + n1 + n2, n3, (size_t)TT * n3);
}

// round 13
// speedup vs baseline: 1.7067x; 1.0637x over previous
#include <cuda_runtime.h>

// Problem constants
#define TT   16
#define BB   512
#define NIN  3072
#define SS1  256
#define SS2  256
#define SS3  128
#define EE   8
#define DECAYF 0.95f
#define KCHUNK 512   // confirmed reference k-partition: 512-chunks, serial ascending fold

typedef unsigned long long ull;

// Persistent scratch (allocation-free: __device__ globals)
__device__ float g_H1[(size_t)EE * TT * BB * SS1]; // 67 MB
__device__ float g_H2[(size_t)EE * TT * BB * SS2]; // 67 MB
__device__ float g_H3[(size_t)EE * TT * BB * SS3]; // 33 MB
__device__ float g_C1[(size_t)TT * BB * SS1];      // 8.4 MB
__device__ float g_C2[(size_t)TT * BB * SS2];      // 8.4 MB

// ---- packed f32x2 helpers: each half is an independent rn op, bit-exact
//      vs the scalar serial chain (verified rel_err==0.0 in R11/R12) ------
__device__ __forceinline__ ull fma2(ull a, ull b, ull c) {
    asm("fma.rn.f32x2 %0, %1, %2, %0;" : "+l"(c) : "l"(a), "l"(b));
    return c;
}
__device__ __forceinline__ ull dup2(float x) {
    ull r; asm("mov.b64 %0, {%1, %1};" : "=l"(r) : "f"(x));
    return r;
}
__device__ __forceinline__ float2 unpk(ull a) {
    float2 r; asm("mov.b64 {%0, %1}, %2;" : "=f"(r.x), "=f"(r.y) : "l"(a));
    return r;
}

// ---------------------------------------------------------------------------
// Batched NT SGEMM, k-chunked (PC=512) fp32 accumulation, packed f32x2 math,
// software-pipelined double-buffered smem (ONE barrier per BK tile; global
// loads issued a full tile ahead of their use).
//   per chunk: fresh accumulator, strictly ascending rn-FMA chain;
//   chunks folded serially ascending via gmem RMW: H = rn(H + P_c)
//   (same CTA owns its tile across chunks -> no race; bit-identical to the
//   register fold). Stages 2/3 (K < PC) take the tail path: plain store.
// BM=BN=128, BK=32, 256 threads; microtile 8 rows (4 f32x2 row-pairs) x 8
// cols (tx*8..tx*8+7: contiguous -> LDS.128). W stored UNduplicated in smem
// (float), duplicated into registers via mov.b64.
// Dynamic smem: 2 * (16KB X + 16KB W) = 64KB.
// M%128==0, N%128==0, K%32==0, PC%32==0.
// ---------------------------------------------------------------------------
__global__ void __launch_bounds__(256, 2) gemm_f32x2(
    const float* __restrict__ X,   // [M][K]
    const float* __restrict__ W,   // [E][N][K]
    float* __restrict__ H,         // [E][M][N]
    int M, int N, int K, int PC)
{
    const int BK = 32, BM = 128, BN = 128;
    extern __shared__ float smem[];          // [2][BK*BM + BK*BN]
    // buffer b: X at b*8192, W at b*8192 + 4096   (floats)

    const int e  = blockIdx.z;
    const int m0 = blockIdx.x * BM;
    const int n0 = blockIdx.y * BN;
    const float* Xp = X + (size_t)m0 * K;
    const float* Wp = W + (size_t)e * N * K + (size_t)n0 * K;
    float*       Hp = H + (size_t)e * M * N;

    const int tid = threadIdx.x;
    const int lr  = tid >> 1;            // loader row 0..127
    const int lc  = (tid & 1) * 16;      // loader k-offset 0 / 16
    const int ty  = tid >> 4;            // 0..15: rows ty*8 .. ty*8+7
    const int tx  = tid & 15;            // 0..15: cols tx*8 .. tx*8+7

    ull accP[4][8];
    #pragma unroll
    for (int p = 0; p < 4; p++)
        #pragma unroll
        for (int j = 0; j < 8; j++) accP[p][j] = 0ULL;

    bool first = true;

    auto fold = [&]() {   // serial ascending chunk fold into gmem (rn adds)
        #pragma unroll
        for (int p = 0; p < 4; p++) {
            float lo[8], hi[8];
            #pragma unroll
            for (int j = 0; j < 8; j++) {
                float2 r = unpk(accP[p][j]);
                lo[j] = r.x; hi[j] = r.y;
                accP[p][j] = 0ULL;
            }
            float* a0 = &Hp[(size_t)(m0 + ty * 8 + 2 * p) * N + n0 + tx * 8];
            float* a1 = a0 + N;
            if (first) {
                *reinterpret_cast<float4*>(a0)     = make_float4(lo[0],lo[1],lo[2],lo[3]);
                *reinterpret_cast<float4*>(a0 + 4) = make_float4(lo[4],lo[5],lo[6],lo[7]);
                *reinterpret_cast<float4*>(a1)     = make_float4(hi[0],hi[1],hi[2],hi[3]);
                *reinterpret_cast<float4*>(a1 + 4) = make_float4(hi[4],hi[5],hi[6],hi[7]);
            } else {
                float4 o0 = *reinterpret_cast<float4*>(a0);
                float4 o1 = *reinterpret_cast<float4*>(a0 + 4);
                float4 o2 = *reinterpret_cast<float4*>(a1);
                float4 o3 = *reinterpret_cast<float4*>(a1 + 4);
                *reinterpret_cast<float4*>(a0)     = make_float4(
                    __fadd_rn(o0.x,lo[0]), __fadd_rn(o0.y,lo[1]),
                    __fadd_rn(o0.z,lo[2]), __fadd_rn(o0.w,lo[3]));
                *reinterpret_cast<float4*>(a0 + 4) = make_float4(
                    __fadd_rn(o1.x,lo[4]), __fadd_rn(o1.y,lo[5]),
                    __fadd_rn(o1.z,lo[6]), __fadd_rn(o1.w,lo[7]));
                *reinterpret_cast<float4*>(a1)     = make_float4(
                    __fadd_rn(o2.x,hi[0]), __fadd_rn(o2.y,hi[1]),
                    __fadd_rn(o2.z,hi[2]), __fadd_rn(o2.w,hi[3]));
                *reinterpret_cast<float4*>(a1 + 4) = make_float4(
                    __fadd_rn(o3.x,hi[4]), __fadd_rn(o3.y,hi[5]),
                    __fadd_rn(o3.z,hi[6]), __fadd_rn(o3.w,hi[7]));
            }
        }
    };

    float4 xv[4], wv[4];
    auto ldg = [&](int k0) {
        #pragma unroll
        for (int q = 0; q < 4; q++)
            xv[q] = *reinterpret_cast<const float4*>(&Xp[(size_t)lr * K + k0 + lc + q * 4]);
        #pragma unroll
        for (int q = 0; q < 4; q++)
            wv[q] = *reinterpret_cast<const float4*>(&Wp[(size_t)lr * K + k0 + lc + q * 4]);
    };
    auto sts = [&](int b) {
        float* Xb = smem + b * 8192;
        float* Wb = Xb + 4096;
        #pragma unroll
        for (int q = 0; q < 4; q++) {
            int kq = lc + q * 4;
            Xb[(kq + 0) * BM + lr] = xv[q].x;
            Xb[(kq + 1) * BM + lr] = xv[q].y;
            Xb[(kq + 2) * BM + lr] = xv[q].z;
            Xb[(kq + 3) * BM + lr] = xv[q].w;
            Wb[(kq + 0) * BN + lr] = wv[q].x;
            Wb[(kq + 1) * BN + lr] = wv[q].y;
            Wb[(kq + 2) * BN + lr] = wv[q].z;
            Wb[(kq + 3) * BN + lr] = wv[q].w;
        }
    };

    // Prologue: tile 0 into buffer 0.
    ldg(0);
    sts(0);
    __syncthreads();

    int cur = 0;
    for (int k0 = 0; k0 < K; k0 += BK) {
        const bool has_next = (k0 + BK) < K;
        if (has_next) ldg(k0 + BK);          // issue a full tile ahead

        const float* Xb = smem + cur * 8192;
        const float* Wb = Xb + 4096;
        #pragma unroll
        for (int kk = 0; kk < BK; kk++) {    // strictly ascending k
            ull xp[4], wp[8];
            const ull* xq = reinterpret_cast<const ull*>(Xb + kk * BM + ty * 8);
            #pragma unroll
            for (int p = 0; p < 4; p++) xp[p] = xq[p];           // LDS.128 x2
            const float* wq = Wb + kk * BN + tx * 8;
            float4 wa = *reinterpret_cast<const float4*>(wq);
            float4 wb2 = *reinterpret_cast<const float4*>(wq + 4);
            wp[0]=dup2(wa.x); wp[1]=dup2(wa.y); wp[2]=dup2(wa.z); wp[3]=dup2(wa.w);
            wp[4]=dup2(wb2.x); wp[5]=dup2(wb2.y); wp[6]=dup2(wb2.z); wp[7]=dup2(wb2.w);
            #pragma unroll
            for (int p = 0; p < 4; p++)
                #pragma unroll
                for (int j = 0; j < 8; j++)
                    accP[p][j] = fma2(xp[p], wp[j], accP[p][j]);
        }

        if (has_next) sts(cur ^ 1);          // fill the other buffer

        // 512-chunk boundary: fold into H (ascending), reset accumulator.
        if (((k0 + BK) % PC) == 0) { fold(); first = false; }

        __syncthreads();                     // one barrier per tile
        cur ^= 1;
    }
    // Tail chunk (K < PC or K % PC != 0): stages 2/3 land here with
    // first==true -> plain store of the single serial chain.
    if ((K % PC) != 0) fold();
}

// ---------------------------------------------------------------------------
// LIF scan over ALL timesteps, 4 elements per thread (float4 path).
// Per-element arithmetic identical to scalar version (separate-rounding):
//   v = rn(rn(v*0.95) + h) ; spk = (v>=1) ; v = rn(v - spk)
//   c = sum_e g[e]*spk ;  mean = (sum_t c) * 1/16  (both exact)
// ---------------------------------------------------------------------------
__global__ void lif_scan4(
    const float* __restrict__ H,    // [E][T][n]
    const float* __restrict__ g,
    float* __restrict__ Cout,       // [T][n] (null: skip)
    float* __restrict__ Omean,      // [n]
    int n, size_t estride)          // estride = T*n
{
    int i4 = (blockIdx.x * blockDim.x + threadIdx.x) * 4;
    if (i4 >= n) return;
    float gv[EE];
    #pragma unroll
    for (int e = 0; e < EE; e++) gv[e] = __ldg(&g[e]);
    float v[EE][4];
    #pragma unroll
    for (int e = 0; e < EE; e++)
        #pragma unroll
        for (int u = 0; u < 4; u++) v[e][u] = 0.f;
    float osum[4] = {0.f, 0.f, 0.f, 0.f};

    for (int t = 0; t < TT; t++) {
        float c[4] = {0.f, 0.f, 0.f, 0.f};
        #pragma unroll
        for (int e = 0; e < EE; e++) {
            float4 h = *reinterpret_cast<const float4*>(
                &H[(size_t)e * estride + (size_t)t * n + i4]);
            float hv[4] = {h.x, h.y, h.z, h.w};
            #pragma unroll
            for (int u = 0; u < 4; u++) {
                float vv  = __fadd_rn(__fmul_rn(v[e][u], DECAYF), hv[u]);
                float spk = (vv >= 1.0f) ? 1.0f : 0.0f;
                v[e][u] = __fsub_rn(vv, spk);
                c[u] = __fadd_rn(c[u], __fmul_rn(gv[e], spk));
            }
        }
        if (Cout)
            *reinterpret_cast<float4*>(&Cout[(size_t)t * n + i4]) =
                make_float4(c[0], c[1], c[2], c[3]);
        #pragma unroll
        for (int u = 0; u < 4; u++) osum[u] = __fadd_rn(osum[u], c[u]);
    }
    *reinterpret_cast<float4*>(&Omean[i4]) = make_float4(
        __fmul_rn(osum[0], 1.0f/(float)TT), __fmul_rn(osum[1], 1.0f/(float)TT),
        __fmul_rn(osum[2], 1.0f/(float)TT), __fmul_rn(osum[3], 1.0f/(float)TT));
}

// ---------------------------------------------------------------------------
extern "C" void kernel_launch(void* const* d_in, const int* in_sizes, int n_in,
                              void* d_out, int out_size) {
    const float* X  = (const float*)d_in[0];  // [16][512][3072]
    const float* W1 = (const float*)d_in[1];  // [8][256][3072]
    const float* W2 = (const float*)d_in[2];  // [8][256][256]
    const float* W3 = (const float*)d_in[3];  // [8][128][256]
    const float* g1 = (const float*)d_in[4];
    const float* g2 = (const float*)d_in[5];
    const float* g3 = (const float*)d_in[6];
    float* out = (float*)d_out;

    float *H1, *H2, *H3, *C1, *C2;
    cudaGetSymbolAddress((void**)&H1, g_H1);
    cudaGetSymbolAddress((void**)&H2, g_H2);
    cudaGetSymbolAddress((void**)&H3, g_H3);
    cudaGetSymbolAddress((void**)&C1, g_C1);
    cudaGetSymbolAddress((void**)&C2, g_C2);

    const int SMEM = 2 * (128 * 32 + 128 * 32) * 4;   // 64 KB
    static bool attr_set = false;
    if (!attr_set) {
        cudaFuncSetAttribute(gemm_f32x2,
            cudaFuncAttributeMaxDynamicSharedMemorySize, SMEM);
        attr_set = true;
    }

    const int M  = TT * BB;              // 8192 rows = (t,b)
    const int n1 = BB * SS1, n2 = BB * SS2, n3 = BB * SS3;

    // Stage 1: one batched GEMM for all t, 512-chunk serial fold.
    gemm_f32x2<<<dim3(M/128, SS1/128, EE), 256, SMEM>>>(X,  W1, H1, M, SS1, NIN, KCHUNK);
    lif_scan4<<<(n1/4 + 255)/256, 256>>>(H1, g1, C1, out,            n1, (size_t)TT * n1);
    // Stage 2: batched over all t (K=256 < 512 -> single serial chain).
    gemm_f32x2<<<dim3(M/128, SS2/128, EE), 256, SMEM>>>(C1, W2, H2, M, SS2, SS1, KCHUNK);
    lif_scan4<<<(n2/4 + 255)/256, 256>>>(H2, g2, C2, out + n1,       n2, (size_t)TT * n2);
    // Stage 3: batched over all t.
    gemm_f32x2<<<dim3(M/128, SS3/128, EE), 256, SMEM>>>(C2, W3, H3, M, SS3, SS2, KCHUNK);
    lif_scan4<<<(n3/4 + 255)/256, 256>>>(H3, g3, nullptr, out + n1 + n2, n3, (size_t)TT * n3);
}

// round 14
// speedup vs baseline: 1.8011x; 1.0553x over previous
#include <cuda_runtime.h>
#include <cstdint>

// Problem constants
#define TT   16
#define BB   512
#define NIN  3072
#define SS1  256
#define SS2  256
#define SS3  128
#define EE   8
#define DECAYF 0.95f
#define KCHUNK 512   // confirmed reference k-partition: 512-chunks, serial ascending fold
#define MM   (TT * BB)   // 8192

typedef unsigned long long ull;

// Persistent scratch (allocation-free: __device__ globals)
__device__ float g_H1[(size_t)EE * MM * SS1];   // 67 MB
__device__ float g_H2[(size_t)EE * MM * SS2];   // 67 MB
__device__ float g_H3[(size_t)EE * MM * SS3];   // 33 MB
__device__ float g_C1[(size_t)MM * SS1];        // 8.4 MB  (row-major [m][o])
__device__ float g_C2[(size_t)MM * SS2];        // 8.4 MB
__device__ float g_Xt [(size_t)NIN * MM];       // 100 MB  X transposed [k][m]
__device__ float g_C1t[(size_t)SS1 * MM];       // 8.4 MB  C1 transposed [k][m]
__device__ float g_C2t[(size_t)SS2 * MM];       // 8.4 MB
__device__ ull   g_W1t[(size_t)EE * NIN * SS1]; // 50 MB   W1 transposed+dup [e][k][n]
__device__ ull   g_W2t[(size_t)EE * SS1 * SS2]; // 4 MB
__device__ ull   g_W3t[(size_t)EE * SS2 * SS3]; // 2 MB

// ---- packed f32x2 helpers: each half is an independent rn op, bit-exact
//      vs the scalar serial chain (verified rel_err==0.0 since R11) -------
__device__ __forceinline__ ull fma2(ull a, ull b, ull c) {
    asm("fma.rn.f32x2 %0, %1, %2, %0;" : "+l"(c) : "l"(a), "l"(b));
    return c;
}
__device__ __forceinline__ ull dup2(float x) {
    ull r; asm("mov.b64 %0, {%1, %1};" : "=l"(r) : "f"(x));
    return r;
}
__device__ __forceinline__ float2 unpk(ull a) {
    float2 r; asm("mov.b64 {%0, %1}, %2;" : "=f"(r.x), "=f"(r.y) : "l"(a));
    return r;
}
__device__ __forceinline__ void cpa16(uint32_t s, const void* g) {
    asm volatile("cp.async.ca.shared.global [%0], [%1], 16;" :: "r"(s), "l"(g));
}

// ---------------------------------------------------------------------------
// Transpose float: src[R][C] -> dst[C][R].  32x32 tiles, 32x8 threads.
// R, C multiples of 32.
// ---------------------------------------------------------------------------
__global__ void transpose_f(const float* __restrict__ src,
                            float* __restrict__ dst, int R, int C) {
    __shared__ float t[32][33];
    int c0 = blockIdx.x * 32, r0 = blockIdx.y * 32;
    int x = threadIdx.x, y = threadIdx.y;
    #pragma unroll
    for (int i = 0; i < 32; i += 8)
        t[y + i][x] = src[(size_t)(r0 + y + i) * C + c0 + x];
    __syncthreads();
    #pragma unroll
    for (int i = 0; i < 32; i += 8)
        dst[(size_t)(c0 + y + i) * R + r0 + x] = t[x][y + i];
}

// ---------------------------------------------------------------------------
// Transpose + duplicate: src[e][N][K] float -> dst[e][K][N] (w,w) ull pairs.
// ---------------------------------------------------------------------------
__global__ void transpose_dup(const float* __restrict__ src,
                              ull* __restrict__ dst, int NN, int KK) {
    __shared__ float t[32][33];
    const float* s = src + (size_t)blockIdx.z * NN * KK;
    ull*         d = dst + (size_t)blockIdx.z * KK * NN;
    int k0 = blockIdx.x * 32, n0 = blockIdx.y * 32;
    int x = threadIdx.x, y = threadIdx.y;
    #pragma unroll
    for (int i = 0; i < 32; i += 8)
        t[y + i][x] = s[(size_t)(n0 + y + i) * KK + k0 + x];
    __syncthreads();
    #pragma unroll
    for (int i = 0; i < 32; i += 8)
        d[(size_t)(k0 + y + i) * NN + n0 + x] = dup2(t[x][y + i]);
}

// ---------------------------------------------------------------------------
// Batched NT SGEMM from k-major inputs via cp.async, packed f32x2 math,
// k-chunked (PC=512) fp32 accumulation:
//   per chunk: fresh accumulator, strictly ascending rn-FMA chain;
//   chunks folded serially ascending via gmem RMW (same CTA owns its tile
//   across chunks -> bit-identical to register fold). Stages 2/3 (K < PC)
//   take the tail path: plain store.
// Xt: [K][M] float (k-major).  Wt: [E][K][N] ull, each entry (w,w).
// BM=BN=128, BK=32, 256 threads; microtile 8 rows (4 f32x2 row-pairs) x 8
// cols {j*16+tx}.  2-stage cp.async pipeline, 48KB/stage (X 16KB + W 32KB).
// M%128==0, N%128==0, K%32==0, PC%32==0.
// ---------------------------------------------------------------------------
__global__ void __launch_bounds__(256, 2) gemm_f32x2(
    const float* __restrict__ Xt,  // [K][M]
    const ull*   __restrict__ Wt,  // [E][K][N] dup'd
    float* __restrict__ H,         // [E][M][N]
    int M, int N, int K, int PC)
{
    const int BK = 32, BM = 128, BN = 128;
    extern __shared__ float smem[];              // 2 stages x 48KB
    const uint32_t sb = (uint32_t)__cvta_generic_to_shared(smem);

    const int e  = blockIdx.z;
    const int m0 = blockIdx.x * BM;
    const int n0 = blockIdx.y * BN;
    float* Hp = H + (size_t)e * M * N;

    const int tid = threadIdx.x;
    const int ty  = tid >> 4;            // 0..15: rows ty*8 .. ty*8+7
    const int tx  = tid & 15;            // 0..15: cols {j*16+tx}

    ull accP[4][8];
    #pragma unroll
    for (int p = 0; p < 4; p++)
        #pragma unroll
        for (int j = 0; j < 8; j++) accP[p][j] = 0ULL;

    bool first = true;

    auto fold = [&]() {   // serial ascending chunk fold into gmem (rn adds)
        #pragma unroll
        for (int p = 0; p < 4; p++) {
            float lo[8], hi[8];
            #pragma unroll
            for (int j = 0; j < 8; j++) {
                float2 r = unpk(accP[p][j]);
                lo[j] = r.x; hi[j] = r.y; accP[p][j] = 0ULL;
            }
            // column of lane tx for j: n0 + j*16 + tx  (scalar stores)
            float* a0 = &Hp[(size_t)(m0 + ty * 8 + 2 * p) * N + n0 + tx];
            float* a1 = a0 + N;
            if (first) {
                #pragma unroll
                for (int j = 0; j < 8; j++) { a0[j*16] = lo[j]; a1[j*16] = hi[j]; }
            } else {
                #pragma unroll
                for (int j = 0; j < 8; j++) {
                    a0[j*16] = __fadd_rn(a0[j*16], lo[j]);
                    a1[j*16] = __fadd_rn(a1[j*16], hi[j]);
                }
            }
        }
    };

    // cp.async one BK-tile (X 16KB + W 32KB) into stage b.
    auto copy_tile = [&](int k0, int b) {
        uint32_t xs = sb + b * 49152;
        uint32_t ws = xs + 16384;
        const float* xsrc = Xt + (size_t)k0 * M + m0;
        #pragma unroll
        for (int i = 0; i < 4; i++) {                 // 1024 granules of 16B
            int g  = tid + i * 256;
            int kk = g >> 5, mc = (g & 31) << 2;
            cpa16(xs + (uint32_t)(kk * BM + mc) * 4, xsrc + (size_t)kk * M + mc);
        }
        const ull* wsrc = Wt + ((size_t)e * K + k0) * N + n0;
        #pragma unroll
        for (int i = 0; i < 8; i++) {                 // 2048 granules of 16B
            int g  = tid + i * 256;
            int kk = g >> 6, nc = (g & 63) << 1;
            cpa16(ws + (uint32_t)(kk * BN + nc) * 8, wsrc + (size_t)kk * N + nc);
        }
        asm volatile("cp.async.commit_group;");
    };

    copy_tile(0, 0);
    int cur = 0;
    for (int k0 = 0; k0 < K; k0 += BK) {
        const bool has_next = (k0 + BK) < K;
        if (has_next) copy_tile(k0 + BK, cur ^ 1);
        if (has_next) asm volatile("cp.async.wait_group 1;");
        else          asm volatile("cp.async.wait_group 0;");
        __syncthreads();                 // tile `cur` visible to all warps

        const float* Xb = smem + cur * 12288;
        const ull*   Wb = reinterpret_cast<const ull*>(smem + cur * 12288 + 4096);
        #pragma unroll
        for (int kk = 0; kk < BK; kk++) {    // strictly ascending k
            ull xp[4], wp[8];
            const ull* xr = reinterpret_cast<const ull*>(Xb + kk * BM) + ty * 4;
            #pragma unroll
            for (int p = 0; p < 4; p++) xp[p] = xr[p];            // LDS.128 x2 (broadcast)
            #pragma unroll
            for (int j = 0; j < 8; j++) wp[j] = Wb[kk * BN + j * 16 + tx]; // conflict-free
            #pragma unroll
            for (int p = 0; p < 4; p++)
                #pragma unroll
                for (int j = 0; j < 8; j++)
                    accP[p][j] = fma2(xp[p], wp[j], accP[p][j]);
        }

        // 512-chunk boundary: fold into H (ascending), reset accumulator.
        if (((k0 + BK) % PC) == 0) { fold(); first = false; }

        __syncthreads();                 // all warps done with `cur` before overwrite
        cur ^= 1;
    }
    // Tail chunk (K < PC or K % PC != 0): stages 2/3 land here, first==true
    // -> plain store of the single serial chain.
    if ((K % PC) != 0) fold();
}

// ---------------------------------------------------------------------------
// LIF scan over ALL timesteps, 4 elements per thread (float4 path).
//   v = rn(rn(v*0.95) + h) ; spk = (v>=1) ; v = rn(v - spk)
//   c = sum_e g[e]*spk ;  mean = (sum_t c) * 1/16  (both exact)
// H layout: [E][M][n_o] with M=(t,b) rows -> slice t is rows t*BB..t*BB+BB.
// ---------------------------------------------------------------------------
__global__ void lif_scan4(
    const float* __restrict__ H,    // [E][M][no] = [E][T*B][no]
    const float* __restrict__ g,
    float* __restrict__ Cout,       // [M][no] (null: skip)
    float* __restrict__ Omean,      // [B*no]
    int no)                         // outputs per (b)
{
    int n = BB * no;                // elements per timestep
    int i4 = (blockIdx.x * blockDim.x + threadIdx.x) * 4;
    if (i4 >= n) return;
    float gv[EE];
    #pragma unroll
    for (int e = 0; e < EE; e++) gv[e] = __ldg(&g[e]);
    float v[EE][4];
    #pragma unroll
    for (int e = 0; e < EE; e++)
        #pragma unroll
        for (int u = 0; u < 4; u++) v[e][u] = 0.f;
    float osum[4] = {0.f, 0.f, 0.f, 0.f};

    for (int t = 0; t < TT; t++) {
        float c[4] = {0.f, 0.f, 0.f, 0.f};
        #pragma unroll
        for (int e = 0; e < EE; e++) {
            float4 h = *reinterpret_cast<const float4*>(
                &H[((size_t)e * MM + (size_t)t * BB) * no + i4]);
            float hv[4] = {h.x, h.y, h.z, h.w};
            #pragma unroll
            for (int u = 0; u < 4; u++) {
                float vv  = __fadd_rn(__fmul_rn(v[e][u], DECAYF), hv[u]);
                float spk = (vv >= 1.0f) ? 1.0f : 0.0f;
                v[e][u] = __fsub_rn(vv, spk);
                c[u] = __fadd_rn(c[u], __fmul_rn(gv[e], spk));
            }
        }
        if (Cout)
            *reinterpret_cast<float4*>(&Cout[(size_t)t * n + i4]) =
                make_float4(c[0], c[1], c[2], c[3]);
        #pragma unroll
        for (int u = 0; u < 4; u++) osum[u] = __fadd_rn(osum[u], c[u]);
    }
    *reinterpret_cast<float4*>(&Omean[i4]) = make_float4(
        __fmul_rn(osum[0], 1.0f/(float)TT), __fmul_rn(osum[1], 1.0f/(float)TT),
        __fmul_rn(osum[2], 1.0f/(float)TT), __fmul_rn(osum[3], 1.0f/(float)TT));
}

// ---------------------------------------------------------------------------
extern "C" void kernel_launch(void* const* d_in, const int* in_sizes, int n_in,
                              void* d_out, int out_size) {
    const float* X  = (const float*)d_in[0];  // [16][512][3072]
    const float* W1 = (const float*)d_in[1];  // [8][256][3072]
    const float* W2 = (const float*)d_in[2];  // [8][256][256]
    const float* W3 = (const float*)d_in[3];  // [8][128][256]
    const float* g1 = (const float*)d_in[4];
    const float* g2 = (const float*)d_in[5];
    const float* g3 = (const float*)d_in[6];
    float* out = (float*)d_out;

    float *H1, *H2, *H3, *C1, *C2, *Xt, *C1t, *C2t;
    ull *W1t, *W2t, *W3t;
    cudaGetSymbolAddress((void**)&H1,  g_H1);
    cudaGetSymbolAddress((void**)&H2,  g_H2);
    cudaGetSymbolAddress((void**)&H3,  g_H3);
    cudaGetSymbolAddress((void**)&C1,  g_C1);
    cudaGetSymbolAddress((void**)&C2,  g_C2);
    cudaGetSymbolAddress((void**)&Xt,  g_Xt);
    cudaGetSymbolAddress((void**)&C1t, g_C1t);
    cudaGetSymbolAddress((void**)&C2t, g_C2t);
    cudaGetSymbolAddress((void**)&W1t, g_W1t);
    cudaGetSymbolAddress((void**)&W2t, g_W2t);
    cudaGetSymbolAddress((void**)&W3t, g_W3t);

    const int SMEM = 2 * 49152;   // 96 KB dynamic
    cudaFuncSetAttribute(gemm_f32x2,
        cudaFuncAttributeMaxDynamicSharedMemorySize, SMEM);

    const int n1 = BB * SS1, n2 = BB * SS2, n3 = BB * SS3;
    dim3 tb(32, 8);

    // ---- Stage 1 ----
    transpose_f  <<<dim3(NIN/32, MM/32),        tb>>>(X, Xt, MM, NIN);
    transpose_dup<<<dim3(NIN/32, SS1/32, EE),   tb>>>(W1, W1t, SS1, NIN);
    gemm_f32x2<<<dim3(MM/128, SS1/128, EE), 256, SMEM>>>(Xt, W1t, H1, MM, SS1, NIN, KCHUNK);
    lif_scan4<<<(n1/4 + 255)/256, 256>>>(H1, g1, C1, out, SS1);

    // ---- Stage 2 ----
    transpose_f  <<<dim3(SS1/32, MM/32),        tb>>>(C1, C1t, MM, SS1);
    transpose_dup<<<dim3(SS1/32, SS2/32, EE),   tb>>>(W2, W2t, SS2, SS1);
    gemm_f32x2<<<dim3(MM/128, SS2/128, EE), 256, SMEM>>>(C1t, W2t, H2, MM, SS2, SS1, KCHUNK);
    lif_scan4<<<(n2/4 + 255)/256, 256>>>(H2, g2, C2, out + n1, SS2);

    // ---- Stage 3 ----
    transpose_f  <<<dim3(SS2/32, MM/32),        tb>>>(C2, C2t, MM, SS2);
    transpose_dup<<<dim3(SS2/32, SS3/32, EE),   tb>>>(W3, W3t, SS3, SS2);
    gemm_f32x2<<<dim3(MM/128, SS3/128, EE), 256, SMEM>>>(C2t, W3t, H3, MM, SS3, SS2, KCHUNK);
    lif_scan4<<<(n3/4 + 255)/256, 256>>>(H3, g3, nullptr, out + n1 + n2, SS3);
}

// round 15
// speedup vs baseline: 2.0584x; 1.1428x over previous
#include <cuda_runtime.h>
#include <cstdint>

// Problem constants
#define TT   16
#define BB   512
#define NIN  3072
#define SS1  256
#define SS2  256
#define SS3  128
#define EE   8
#define DECAYF 0.95f
#define KCHUNK 512   // confirmed reference k-partition: 512-chunks, serial ascending fold
#define MM   (TT * BB)   // 8192

typedef unsigned long long ull;

// Persistent scratch (allocation-free: __device__ globals)
__device__ float g_H1[(size_t)EE * MM * SS1];   // 67 MB
__device__ float g_H2[(size_t)EE * MM * SS2];   // 67 MB
__device__ float g_H3[(size_t)EE * MM * SS3];   // 33 MB
__device__ float g_C1[(size_t)MM * SS1];        // 8.4 MB  (row-major [m][o])
__device__ float g_C2[(size_t)MM * SS2];        // 8.4 MB
__device__ float g_Xt [(size_t)NIN * MM];       // 100 MB  X transposed [k][m]
__device__ float g_C1t[(size_t)SS1 * MM];       // 8.4 MB
__device__ float g_C2t[(size_t)SS2 * MM];       // 8.4 MB
__device__ float g_W1t[(size_t)EE * NIN * SS1]; // 25 MB   W1 transposed [e][k][n]
__device__ float g_W2t[(size_t)EE * SS1 * SS2]; // 2 MB
__device__ float g_W3t[(size_t)EE * SS2 * SS3]; // 1 MB

// ---- packed f32x2 helpers: each half is an independent rn op, bit-exact
//      vs the scalar serial chain (verified rel_err==0.0 since R11) -------
__device__ __forceinline__ ull fma2(ull a, ull b, ull c) {
    asm("fma.rn.f32x2 %0, %1, %2, %0;" : "+l"(c) : "l"(a), "l"(b));
    return c;
}
__device__ __forceinline__ ull dup2(float x) {
    ull r; asm("mov.b64 %0, {%1, %1};" : "=l"(r) : "f"(x));
    return r;
}
__device__ __forceinline__ float2 unpk(ull a) {
    float2 r; asm("mov.b64 {%0, %1}, %2;" : "=f"(r.x), "=f"(r.y) : "l"(a));
    return r;
}
__device__ __forceinline__ void cpa16(uint32_t s, const void* g) {
    asm volatile("cp.async.ca.shared.global [%0], [%1], 16;" :: "r"(s), "l"(g));
}

// ---------------------------------------------------------------------------
// Batched transpose: src[z][R][C] -> dst[z][C][R]. 32x32 tiles, 32x8 threads.
// R, C multiples of 32.
// ---------------------------------------------------------------------------
__global__ void transpose_b(const float* __restrict__ src,
                            float* __restrict__ dst, int R, int C) {
    __shared__ float t[32][33];
    const float* s = src + (size_t)blockIdx.z * R * C;
    float*       d = dst + (size_t)blockIdx.z * R * C;
    int c0 = blockIdx.x * 32, r0 = blockIdx.y * 32;
    int x = threadIdx.x, y = threadIdx.y;
    #pragma unroll
    for (int i = 0; i < 32; i += 8)
        t[y + i][x] = s[(size_t)(r0 + y + i) * C + c0 + x];
    __syncthreads();
    #pragma unroll
    for (int i = 0; i < 32; i += 8)
        d[(size_t)(c0 + y + i) * R + r0 + x] = t[x][y + i];
}

// ---------------------------------------------------------------------------
// Batched NT SGEMM from k-major inputs, packed f32x2, k-chunked (PC=512)
// fp32 accumulation:
//   per chunk: fresh accumulator, strictly ascending rn-FMA chain;
//   chunks folded serially ascending via gmem RMW (CTA owns its tile across
//   chunks -> bit-identical to the register fold). K < PC -> plain store.
// Xt: [K][M] float.  Wt: [E][K][N] float (UNduplicated; dup'd into regs).
// BM=64, BN=128, BK=32, 256 threads; microtile 4 rows (2 f32x2 row-pairs) x
// 8 cols (tx*4+{0..3} and 64+tx*4+{0..3} -> W reads are 2x LDS.128).
// Ring-3 cp.async pipeline (24KB/stage), copies 2 tiles ahead, ONE barrier
// per tile. M%64==0, N%128==0, K%32==0, PC%32==0.
// ---------------------------------------------------------------------------
__global__ void __launch_bounds__(256, 2) gemm_f32x2(
    const float* __restrict__ Xt,  // [K][M]
    const float* __restrict__ Wt,  // [E][K][N]
    float* __restrict__ H,         // [E][M][N]
    int M, int N, int K, int PC)
{
    const int BK = 32, BM = 64, BN = 128;
    extern __shared__ float smem[];              // 3 stages x 6144 floats
    const uint32_t sb = (uint32_t)__cvta_generic_to_shared(smem);

    const int e  = blockIdx.z;
    const int m0 = blockIdx.x * BM;
    const int n0 = blockIdx.y * BN;
    float* Hp = H + (size_t)e * M * N;

    const int tid = threadIdx.x;
    const int ty  = tid >> 4;            // 0..15: rows ty*4 .. ty*4+3
    const int tx  = tid & 15;            // 0..15: cols tx*4+{0..3}, 64+tx*4+{0..3}

    ull accP[2][8];
    #pragma unroll
    for (int p = 0; p < 2; p++)
        #pragma unroll
        for (int j = 0; j < 8; j++) accP[p][j] = 0ULL;

    bool first = true;

    auto fold = [&]() {   // serial ascending chunk fold into gmem (rn adds)
        #pragma unroll
        for (int p = 0; p < 2; p++) {
            float lo[8], hi[8];
            #pragma unroll
            for (int j = 0; j < 8; j++) {
                float2 r = unpk(accP[p][j]);
                lo[j] = r.x; hi[j] = r.y; accP[p][j] = 0ULL;
            }
            float* a0 = &Hp[(size_t)(m0 + ty * 4 + 2 * p) * N + n0];
            float* a1 = a0 + N;
            if (first) {
                *reinterpret_cast<float4*>(a0 + tx*4)      = make_float4(lo[0],lo[1],lo[2],lo[3]);
                *reinterpret_cast<float4*>(a0 + 64 + tx*4) = make_float4(lo[4],lo[5],lo[6],lo[7]);
                *reinterpret_cast<float4*>(a1 + tx*4)      = make_float4(hi[0],hi[1],hi[2],hi[3]);
                *reinterpret_cast<float4*>(a1 + 64 + tx*4) = make_float4(hi[4],hi[5],hi[6],hi[7]);
            } else {
                float4 o0 = *reinterpret_cast<float4*>(a0 + tx*4);
                float4 o1 = *reinterpret_cast<float4*>(a0 + 64 + tx*4);
                float4 o2 = *reinterpret_cast<float4*>(a1 + tx*4);
                float4 o3 = *reinterpret_cast<float4*>(a1 + 64 + tx*4);
                *reinterpret_cast<float4*>(a0 + tx*4)      = make_float4(
                    __fadd_rn(o0.x,lo[0]), __fadd_rn(o0.y,lo[1]),
                    __fadd_rn(o0.z,lo[2]), __fadd_rn(o0.w,lo[3]));
                *reinterpret_cast<float4*>(a0 + 64 + tx*4) = make_float4(
                    __fadd_rn(o1.x,lo[4]), __fadd_rn(o1.y,lo[5]),
                    __fadd_rn(o1.z,lo[6]), __fadd_rn(o1.w,lo[7]));
                *reinterpret_cast<float4*>(a1 + tx*4)      = make_float4(
                    __fadd_rn(o2.x,hi[0]), __fadd_rn(o2.y,hi[1]),
                    __fadd_rn(o2.z,hi[2]), __fadd_rn(o2.w,hi[3]));
                *reinterpret_cast<float4*>(a1 + 64 + tx*4) = make_float4(
                    __fadd_rn(o3.x,hi[4]), __fadd_rn(o3.y,hi[5]),
                    __fadd_rn(o3.z,hi[6]), __fadd_rn(o3.w,hi[7]));
            }
        }
    };

    // cp.async one BK-tile (X 8KB + W 16KB) into ring stage s.
    auto copy_tile = [&](int k0, int s) {
        uint32_t xs = sb + (uint32_t)s * 24576;
        uint32_t ws = xs + 8192;
        const float* xsrc = Xt + (size_t)k0 * M + m0;
        #pragma unroll
        for (int i = 0; i < 2; i++) {                 // 512 granules of 16B
            int g  = tid + i * 256;
            int kk = g >> 4, mc = (g & 15) << 2;
            cpa16(xs + (uint32_t)(kk * BM + mc) * 4, xsrc + (size_t)kk * M + mc);
        }
        const float* wsrc = Wt + ((size_t)e * K + k0) * N + n0;
        #pragma unroll
        for (int i = 0; i < 4; i++) {                 // 1024 granules of 16B
            int g  = tid + i * 256;
            int kk = g >> 5, nc = (g & 31) << 2;
            cpa16(ws + (uint32_t)(kk * BN + nc) * 4, wsrc + (size_t)kk * N + nc);
        }
        asm volatile("cp.async.commit_group;");
    };

    const int nt = K / BK;
    copy_tile(0, 0);
    if (nt > 1) copy_tile(BK, 1);

    for (int i = 0; i < nt; i++) {
        const int k0 = i * BK;
        // Wait for tile i (leave tile i+1 in flight if it exists).
        if (i < nt - 1) asm volatile("cp.async.wait_group 1;");
        else            asm volatile("cp.async.wait_group 0;");
        __syncthreads();   // (a) tile i visible to all; (b) all warps done
                           // with stage (i+2)%3 (tile i-1 computed before)
        if (i + 2 < nt) copy_tile(k0 + 2 * BK, (i + 2) % 3);

        const float* Xb = smem + (i % 3) * 6144;
        const float* Wb = Xb + 2048;
        #pragma unroll
        for (int kk = 0; kk < BK; kk++) {    // strictly ascending k
            ull xp[2], wp[8];
            const ull* xr = reinterpret_cast<const ull*>(Xb + kk * BM + ty * 4);
            xp[0] = xr[0]; xp[1] = xr[1];                  // LDS.128 (broadcast)
            const float* wq = Wb + kk * BN + tx * 4;
            float4 wa = *reinterpret_cast<const float4*>(wq);
            float4 wc = *reinterpret_cast<const float4*>(wq + 64);
            wp[0]=dup2(wa.x); wp[1]=dup2(wa.y); wp[2]=dup2(wa.z); wp[3]=dup2(wa.w);
            wp[4]=dup2(wc.x); wp[5]=dup2(wc.y); wp[6]=dup2(wc.z); wp[7]=dup2(wc.w);
            #pragma unroll
            for (int p = 0; p < 2; p++)
                #pragma unroll
                for (int j = 0; j < 8; j++)
                    accP[p][j] = fma2(xp[p], wp[j], accP[p][j]);
        }

        // 512-chunk boundary: fold into H (ascending), reset accumulator.
        if (((k0 + BK) % PC) == 0) { fold(); first = false; }
    }
    // Tail chunk (K < PC or K % PC != 0): plain store / final RMW.
    if ((K % PC) != 0) fold();
}

// ---------------------------------------------------------------------------
// LIF scan over ALL timesteps, 4 elements per thread (float4 path).
//   v = rn(rn(v*0.95) + h) ; spk = (v>=1) ; v = rn(v - spk)
//   c = sum_e g[e]*spk ;  mean = (sum_t c) * 1/16  (both exact)
// ---------------------------------------------------------------------------
__global__ void lif_scan4(
    const float* __restrict__ H,    // [E][M][no]
    const float* __restrict__ g,
    float* __restrict__ Cout,       // [M][no] (null: skip)
    float* __restrict__ Omean,      // [B*no]
    int no)
{
    int n = BB * no;
    int i4 = (blockIdx.x * blockDim.x + threadIdx.x) * 4;
    if (i4 >= n) return;
    float gv[EE];
    #pragma unroll
    for (int e = 0; e < EE; e++) gv[e] = __ldg(&g[e]);
    float v[EE][4];
    #pragma unroll
    for (int e = 0; e < EE; e++)
        #pragma unroll
        for (int u = 0; u < 4; u++) v[e][u] = 0.f;
    float osum[4] = {0.f, 0.f, 0.f, 0.f};

    for (int t = 0; t < TT; t++) {
        float c[4] = {0.f, 0.f, 0.f, 0.f};
        #pragma unroll
        for (int e = 0; e < EE; e++) {
            float4 h = *reinterpret_cast<const float4*>(
                &H[((size_t)e * MM + (size_t)t * BB) * no + i4]);
            float hv[4] = {h.x, h.y, h.z, h.w};
            #pragma unroll
            for (int u = 0; u < 4; u++) {
                float vv  = __fadd_rn(__fmul_rn(v[e][u], DECAYF), hv[u]);
                float spk = (vv >= 1.0f) ? 1.0f : 0.0f;
                v[e][u] = __fsub_rn(vv, spk);
                c[u] = __fadd_rn(c[u], __fmul_rn(gv[e], spk));
            }
        }
        if (Cout)
            *reinterpret_cast<float4*>(&Cout[(size_t)t * n + i4]) =
                make_float4(c[0], c[1], c[2], c[3]);
        #pragma unroll
        for (int u = 0; u < 4; u++) osum[u] = __fadd_rn(osum[u], c[u]);
    }
    *reinterpret_cast<float4*>(&Omean[i4]) = make_float4(
        __fmul_rn(osum[0], 1.0f/(float)TT), __fmul_rn(osum[1], 1.0f/(float)TT),
        __fmul_rn(osum[2], 1.0f/(float)TT), __fmul_rn(osum[3], 1.0f/(float)TT));
}

// ---------------------------------------------------------------------------
extern "C" void kernel_launch(void* const* d_in, const int* in_sizes, int n_in,
                              void* d_out, int out_size) {
    const float* X  = (const float*)d_in[0];  // [16][512][3072]
    const float* W1 = (const float*)d_in[1];  // [8][256][3072]
    const float* W2 = (const float*)d_in[2];  // [8][256][256]
    const float* W3 = (const float*)d_in[3];  // [8][128][256]
    const float* g1 = (const float*)d_in[4];
    const float* g2 = (const float*)d_in[5];
    const float* g3 = (const float*)d_in[6];
    float* out = (float*)d_out;

    float *H1, *H2, *H3, *C1, *C2, *Xt, *C1t, *C2t, *W1t, *W2t, *W3t;
    cudaGetSymbolAddress((void**)&H1,  g_H1);
    cudaGetSymbolAddress((void**)&H2,  g_H2);
    cudaGetSymbolAddress((void**)&H3,  g_H3);
    cudaGetSymbolAddress((void**)&C1,  g_C1);
    cudaGetSymbolAddress((void**)&C2,  g_C2);
    cudaGetSymbolAddress((void**)&Xt,  g_Xt);
    cudaGetSymbolAddress((void**)&C1t, g_C1t);
    cudaGetSymbolAddress((void**)&C2t, g_C2t);
    cudaGetSymbolAddress((void**)&W1t, g_W1t);
    cudaGetSymbolAddress((void**)&W2t, g_W2t);
    cudaGetSymbolAddress((void**)&W3t, g_W3t);

    const int SMEM = 3 * 24576;   // 72 KB dynamic
    static bool attr_set = false;
    if (!attr_set) {
        cudaFuncSetAttribute(gemm_f32x2,
            cudaFuncAttributeMaxDynamicSharedMemorySize, SMEM);
        attr_set = true;
    }

    const int n1 = BB * SS1, n2 = BB * SS2, n3 = BB * SS3;
    dim3 tb(32, 8);

    // ---- Stage 1 ----
    transpose_b<<<dim3(NIN/32, MM/32, 1),   tb>>>(X,  Xt,  MM,  NIN);
    transpose_b<<<dim3(NIN/32, SS1/32, EE), tb>>>(W1, W1t, SS1, NIN);
    gemm_f32x2<<<dim3(MM/64, SS1/128, EE), 256, SMEM>>>(Xt, W1t, H1, MM, SS1, NIN, KCHUNK);
    lif_scan4<<<(n1/4 + 255)/256, 256>>>(H1, g1, C1, out, SS1);

    // ---- Stage 2 ----
    transpose_b<<<dim3(SS1/32, MM/32, 1),   tb>>>(C1, C1t, MM,  SS1);
    transpose_b<<<dim3(SS1/32, SS2/32, EE), tb>>>(W2, W2t, SS2, SS1);
    gemm_f32x2<<<dim3(MM/64, SS2/128, EE), 256, SMEM>>>(C1t, W2t, H2, MM, SS2, SS1, KCHUNK);
    lif_scan4<<<(n2/4 + 255)/256, 256>>>(H2, g2, C2, out + n1, SS2);

    // ---- Stage 3 ----
    transpose_b<<<dim3(SS2/32, MM/32, 1),   tb>>>(C2, C2t, MM,  SS2);
    transpose_b<<<dim3(SS2/32, SS3/32, EE), tb>>>(W3, W3t, SS3, SS2);
    gemm_f32x2<<<dim3(MM/64, SS3/128, EE), 256, SMEM>>>(C2t, W3t, H3, MM, SS3, SS2, KCHUNK);
    lif_scan4<<<(n3/4 + 255)/256, 256>>>(H3, g3, nullptr, out + n1 + n2, SS3);
}